// round 1
// baseline (speedup 1.0000x reference)
#include <cuda_runtime.h>
#include <math_constants.h>

// Problem constants
constexpr int Bc  = 4;
constexpr int Sc  = 2048;
constexpr int Ec  = 512;
constexpr int Hc  = 8;
constexpr int DKc = 64;

// Scratch (static device globals: allocation-free per harness rules)
__device__ float g_A [Bc * Hc * Sc * DKc];  // cos(x+theta), layout [b][h][s][d]
__device__ float g_AO[Bc * Sc * Ec];        // attention output, layout [b][s][e]

// ---------------------------------------------------------------------------
// Kernel 1: A[b,h,s,d] = cos(x[b,s,h*64+d] + theta[d])
// ---------------------------------------------------------------------------
__global__ __launch_bounds__(256) void cos_kernel(const float* __restrict__ x,
                                                  const float* __restrict__ theta) {
    int idx = blockIdx.x * 256 + threadIdx.x;          // over B*S*E
    int e   = idx & (Ec - 1);
    int bs  = idx >> 9;                                // / 512
    int d   = e & (DKc - 1);
    int h   = e >> 6;
    int b   = bs >> 11;                                // / 2048
    int s   = bs & (Sc - 1);
    g_A[(((size_t)(b * Hc + h) * Sc) + s) * DKc + d] = cosf(x[idx] + theta[d]);
}

// ---------------------------------------------------------------------------
// Kernel 2: flash attention, Q=K=V=A. One block = 64 query rows of one (b,h).
// 256 threads = 8 warps; warp w owns query rows w*8 .. w*8+7.
// Lane owns key/val columns {lane, lane+32} (conflict-free smem access).
// ---------------------------------------------------------------------------
__global__ __launch_bounds__(256) void flash_kernel() {
    __shared__ float Qs[64][65];
    __shared__ float Ks[64][65];   // also serves as the V tile (V == K)
    __shared__ float Ps[64][65];   // probs; warp-private row ranges

    const int qt = blockIdx.x, h = blockIdx.y, b = blockIdx.z;
    const float* Abh = g_A + (size_t)(b * Hc + h) * Sc * DKc;

    const int tid  = threadIdx.x;
    const int lane = tid & 31;
    const int w    = tid >> 5;
    const int lr0  = w * 8;
    const int c0   = lane, c1 = lane + 32;

    // Load Q tile once
    for (int i = tid; i < 64 * 64; i += 256) {
        int r = i >> 6, c = i & 63;
        Qs[r][c] = Abh[(size_t)(qt * 64 + r) * DKc + c];
    }

    float m[8], l[8], o0[8], o1[8];
#pragma unroll
    for (int i = 0; i < 8; i++) { m[i] = -CUDART_INF_F; l[i] = 0.f; o0[i] = 0.f; o1[i] = 0.f; }

    for (int kt = 0; kt < Sc / 64; kt++) {
        __syncthreads();
        for (int i = tid; i < 64 * 64; i += 256) {
            int r = i >> 6, c = i & 63;
            Ks[r][c] = Abh[(size_t)(kt * 64 + r) * DKc + c];
        }
        __syncthreads();

        // ---- scores: s[ri][{c0,c1}] = sum_d Q[row][d] * K[col][d]
        float s0[8], s1[8];
#pragma unroll
        for (int i = 0; i < 8; i++) { s0[i] = 0.f; s1[i] = 0.f; }

#pragma unroll 8
        for (int d = 0; d < 64; d++) {
            float k0 = Ks[c0][d];
            float k1 = Ks[c1][d];
#pragma unroll
            for (int ri = 0; ri < 8; ri++) {
                float q = Qs[lr0 + ri][d];
                s0[ri] = fmaf(q, k0, s0[ri]);
                s1[ri] = fmaf(q, k1, s1[ri]);
            }
        }

        // ---- online softmax per row (warp-wide: 64 cols across 32 lanes)
#pragma unroll
        for (int ri = 0; ri < 8; ri++) {
            float a0 = s0[ri] * 0.125f;       // 1/sqrt(64)
            float a1 = s1[ri] * 0.125f;
            float mx = fmaxf(a0, a1);
#pragma unroll
            for (int off = 16; off > 0; off >>= 1)
                mx = fmaxf(mx, __shfl_xor_sync(0xffffffffu, mx, off));
            float mnew  = fmaxf(m[ri], mx);
            float p0    = __expf(a0 - mnew);
            float p1    = __expf(a1 - mnew);
            float alpha = __expf(m[ri] - mnew);   // exp(-inf)=0 on first tile
            float rs    = p0 + p1;
#pragma unroll
            for (int off = 16; off > 0; off >>= 1)
                rs += __shfl_xor_sync(0xffffffffu, rs, off);
            l[ri]  = l[ri] * alpha + rs;
            m[ri]  = mnew;
            o0[ri] *= alpha;
            o1[ri] *= alpha;
            Ps[lr0 + ri][c0] = p0;
            Ps[lr0 + ri][c1] = p1;
        }
        __syncwarp();

        // ---- O += P @ V   (V tile == Ks; lane owns d-cols {c0, c1})
#pragma unroll 8
        for (int k = 0; k < 64; k++) {
            float v0 = Ks[k][c0];
            float v1 = Ks[k][c1];
#pragma unroll
            for (int ri = 0; ri < 8; ri++) {
                float p = Ps[lr0 + ri][k];
                o0[ri] = fmaf(p, v0, o0[ri]);
                o1[ri] = fmaf(p, v1, o1[ri]);
            }
        }
    }

    // ---- write normalized output in [b][s][e] layout (e = h*64 + d)
#pragma unroll
    for (int ri = 0; ri < 8; ri++) {
        int qr = qt * 64 + lr0 + ri;
        float inv = 1.0f / l[ri];
        float* outp = g_AO + ((size_t)(b * Sc + qr)) * Ec + h * DKc;
        outp[c0] = o0[ri] * inv;
        outp[c1] = o1[ri] * inv;
    }
}

// ---------------------------------------------------------------------------
// Kernel 3: out[m][n] = sum_k AO[m][k] * W[n][k] + bias[n]
// M=8192, N=512, K=512. 64x64 tile, BK=16, 256 threads, 4x4 per thread.
// ---------------------------------------------------------------------------
__global__ __launch_bounds__(256) void gemm_kernel(const float* __restrict__ W,
                                                   const float* __restrict__ bias,
                                                   float* __restrict__ out) {
    __shared__ float As[64][17];
    __shared__ float Ws[64][17];

    const int m0 = blockIdx.y * 64;
    const int n0 = blockIdx.x * 64;
    const int tid = threadIdx.x;
    const int tx = tid & 15, ty = tid >> 4;

    float acc[4][4] = {};

    for (int k0 = 0; k0 < Ec; k0 += 16) {
        __syncthreads();
        for (int i = tid; i < 64 * 16; i += 256) {
            int r = i >> 4, c = i & 15;
            As[r][c] = g_AO[(size_t)(m0 + r) * Ec + k0 + c];
            Ws[r][c] = W   [(size_t)(n0 + r) * Ec + k0 + c];
        }
        __syncthreads();
#pragma unroll
        for (int kk = 0; kk < 16; kk++) {
            float a[4], wv[4];
#pragma unroll
            for (int i = 0; i < 4; i++) { a[i] = As[ty * 4 + i][kk]; wv[i] = Ws[tx * 4 + i][kk]; }
#pragma unroll
            for (int i = 0; i < 4; i++)
#pragma unroll
                for (int j = 0; j < 4; j++)
                    acc[i][j] = fmaf(a[i], wv[j], acc[i][j]);
        }
    }

#pragma unroll
    for (int i = 0; i < 4; i++) {
        int mrow = m0 + ty * 4 + i;
#pragma unroll
        for (int j = 0; j < 4; j++) {
            int ncol = n0 + tx * 4 + j;
            out[(size_t)mrow * Ec + ncol] = acc[i][j] + bias[ncol];
        }
    }
}

// ---------------------------------------------------------------------------
extern "C" void kernel_launch(void* const* d_in, const int* in_sizes, int n_in,
                              void* d_out, int out_size) {
    const float* x     = (const float*)d_in[0];  // [4,2048,512]
    const float* theta = (const float*)d_in[1];  // [64]
    const float* W     = (const float*)d_in[2];  // [512,512]
    const float* bias  = (const float*)d_in[3];  // [512]
    float* out = (float*)d_out;                  // [4,2048,512]

    // 1) quantum projection: A = cos(x + theta) in head-major layout
    cos_kernel<<<(Bc * Sc * Ec) / 256, 256>>>(x, theta);

    // 2) flash attention (Q=K=V=A)
    dim3 fgrid(Sc / 64, Hc, Bc);
    flash_kernel<<<fgrid, 256>>>();

    // 3) epilogue GEMM + bias
    dim3 ggrid(Ec / 64, (Bc * Sc) / 64);
    gemm_kernel<<<ggrid, 256>>>(W, bias, out);
}

// round 3
// speedup vs baseline: 3.5313x; 3.5313x over previous
#include <cuda_runtime.h>
#include <cuda_bf16.h>
#include <cstdint>

constexpr int Bc = 4, Sc = 2048, Ec = 512, Hc = 8, DKc = 64;

__device__ __align__(256) __nv_bfloat16 g_Ahi [Bc * Hc * Sc * DKc];
__device__ __align__(256) __nv_bfloat16 g_Alo [Bc * Hc * Sc * DKc];
__device__ __align__(256) __nv_bfloat16 g_AOhi[Bc * Sc * Ec];
__device__ __align__(256) __nv_bfloat16 g_AOlo[Bc * Sc * Ec];
__device__ __align__(256) __nv_bfloat16 g_Whi [Ec * Ec];
__device__ __align__(256) __nv_bfloat16 g_Wlo [Ec * Ec];

// ---------------------------------------------------------------------------
// helpers
// ---------------------------------------------------------------------------
__device__ __forceinline__ uint32_t smem_u32(const void* p) {
    uint32_t a;
    asm("{ .reg .u64 t; cvta.to.shared.u64 t, %1; cvt.u32.u64 %0, t; }" : "=r"(a) : "l"(p));
    return a;
}
__device__ __forceinline__ void ldsm_x4(uint32_t* r, uint32_t addr) {
    asm volatile("ldmatrix.sync.aligned.m8n8.x4.shared.b16 {%0,%1,%2,%3}, [%4];"
                 : "=r"(r[0]), "=r"(r[1]), "=r"(r[2]), "=r"(r[3]) : "r"(addr));
}
__device__ __forceinline__ void ldsm_x4_t(uint32_t* r, uint32_t addr) {
    asm volatile("ldmatrix.sync.aligned.m8n8.x4.trans.shared.b16 {%0,%1,%2,%3}, [%4];"
                 : "=r"(r[0]), "=r"(r[1]), "=r"(r[2]), "=r"(r[3]) : "r"(addr));
}
__device__ __forceinline__ void mma_bf16(float* d, const uint32_t* a, const uint32_t* b) {
    asm volatile("mma.sync.aligned.m16n8k16.row.col.f32.bf16.bf16.f32 "
                 "{%0,%1,%2,%3}, {%4,%5,%6,%7}, {%8,%9}, {%0,%1,%2,%3};"
                 : "+f"(d[0]), "+f"(d[1]), "+f"(d[2]), "+f"(d[3])
                 : "r"(a[0]), "r"(a[1]), "r"(a[2]), "r"(a[3]), "r"(b[0]), "r"(b[1]));
}
__device__ __forceinline__ float ex2f(float x) {
    float y; asm("ex2.approx.f32 %0, %1;" : "=f"(y) : "f"(x)); return y;
}
// split x0,x1 into packed bf16 hi (truncation, exact) + packed bf16 lo (residual)
__device__ __forceinline__ void split2(float x0, float x1, uint32_t& hp, uint32_t& lp) {
    uint32_t u0 = __float_as_uint(x0) & 0xffff0000u;
    uint32_t u1 = __float_as_uint(x1) & 0xffff0000u;
    hp = u1 | (u0 >> 16);
    float r0 = x0 - __uint_as_float(u0);
    float r1 = x1 - __uint_as_float(u1);
    asm("cvt.rn.bf16x2.f32 %0, %1, %2;" : "=r"(lp) : "f"(r1), "f"(r0));
}

#define CP_COMMIT asm volatile("cp.async.commit_group;" ::: "memory")
#define CP_WAIT0  asm volatile("cp.async.wait_group 0;" ::: "memory")
#define CP_WAIT1  asm volatile("cp.async.wait_group 1;" ::: "memory")

// copy rows x 128B (64 bf16) tile from gmem (row stride in elems) to SW-swizzled smem
__device__ __forceinline__ void cpa_tile(uint32_t sdst, const __nv_bfloat16* g,
                                         int rows, int stride, int tid) {
    int n = rows * 8;
    for (int idx = tid; idx < n; idx += 256) {
        int r = idx >> 3, c = idx & 7;
        uint32_t d = sdst + r * 128 + ((c ^ (r & 7)) << 4);
        const __nv_bfloat16* s = g + (size_t)r * stride + c * 8;
        asm volatile("cp.async.cg.shared.global [%0], [%1], 16;" :: "r"(d), "l"(s));
    }
}

constexpr float SCL = 0.18033688011112042f;  // log2(e)/8

// ---------------------------------------------------------------------------
// Kernel 1: A = cos(x+theta), bf16 hi/lo split, head-major layout
// ---------------------------------------------------------------------------
__global__ __launch_bounds__(256) void cos_split_kernel(const float* __restrict__ x,
                                                        const float* __restrict__ theta) {
    int t = blockIdx.x * 256 + threadIdx.x;
    int base = t * 4;
    int e = base & (Ec - 1), bs = base >> 9;
    int d = e & (DKc - 1), h = e >> 6;
    int b = bs >> 11, s = bs & (Sc - 1);

    float4 xv = *reinterpret_cast<const float4*>(x + base);
    float4 tv = *reinterpret_cast<const float4*>(theta + d);
    float c0 = cosf(xv.x + tv.x), c1 = cosf(xv.y + tv.y);
    float c2 = cosf(xv.z + tv.z), c3 = cosf(xv.w + tv.w);

    uint32_t hp0, lp0, hp1, lp1;
    split2(c0, c1, hp0, lp0);
    split2(c2, c3, hp1, lp1);
    size_t o = (((size_t)(b * Hc + h) * Sc) + s) * DKc + d;
    *reinterpret_cast<uint2*>(&g_Ahi[o]) = make_uint2(hp0, hp1);
    *reinterpret_cast<uint2*>(&g_Alo[o]) = make_uint2(lp0, lp1);
}

// ---------------------------------------------------------------------------
// Kernel 2: W hi/lo split
// ---------------------------------------------------------------------------
__global__ __launch_bounds__(256) void w_split_kernel(const float* __restrict__ W) {
    int base = (blockIdx.x * 256 + threadIdx.x) * 4;
    float4 wv = *reinterpret_cast<const float4*>(W + base);
    uint32_t hp0, lp0, hp1, lp1;
    split2(wv.x, wv.y, hp0, lp0);
    split2(wv.z, wv.w, hp1, lp1);
    *reinterpret_cast<uint2*>(&g_Whi[base]) = make_uint2(hp0, hp1);
    *reinterpret_cast<uint2*>(&g_Wlo[base]) = make_uint2(lp0, lp1);
}

// ---------------------------------------------------------------------------
// Kernel 3: flash attention via mma.sync (Q=K=V), bf16 3-term, bounded softmax
// ---------------------------------------------------------------------------
constexpr int SM_QHI = 0;
constexpr int SM_QLO = 16384;
constexpr int SM_KB  = 32768;          // K buf i at SM_KB + i*16384 (hi), +8192 (lo)
constexpr int FL_SMEM = 65536;

__global__ void __launch_bounds__(256) flash_mma_kernel() {
    extern __shared__ char smem[];
    const uint32_t sb = smem_u32(smem);
    const int tid = threadIdx.x, lane = tid & 31, w = tid >> 5;
    const int qt = blockIdx.x, h = blockIdx.y, b = blockIdx.z;
    const int bh = b * Hc + h;
    const __nv_bfloat16* Ahi = g_Ahi + (size_t)bh * Sc * DKc;
    const __nv_bfloat16* Alo = g_Alo + (size_t)bh * Sc * DKc;

    // prologue: Q tile (group 0), K0 (group 1), K1 (group 2)
    cpa_tile(sb + SM_QHI, Ahi + qt * 128 * 64, 128, 64, tid);
    cpa_tile(sb + SM_QLO, Alo + qt * 128 * 64, 128, 64, tid);
    CP_COMMIT;
    cpa_tile(sb + SM_KB,        Ahi, 64, 64, tid);
    cpa_tile(sb + SM_KB + 8192, Alo, 64, 64, tid);
    CP_COMMIT;
    cpa_tile(sb + SM_KB + 16384,        Ahi + 64 * 64, 64, 64, tid);
    cpa_tile(sb + SM_KB + 16384 + 8192, Alo + 64 * 64, 64, 64, tid);
    CP_COMMIT;
    CP_WAIT1;                  // Q + K0 landed
    __syncthreads();

    // Q fragments (persist across whole loop)
    uint32_t qh[16], ql[16];
    {
        int row = 16 * w + (lane & 7) + (((lane >> 3) & 1) << 3);
#pragma unroll
        for (int ks = 0; ks < 4; ks++) {
            int c = 2 * ks + (lane >> 4);
            uint32_t a = sb + SM_QHI + row * 128 + ((c ^ (row & 7)) << 4);
            ldsm_x4(qh + ks * 4, a);
            ldsm_x4(ql + ks * 4, a + 16384);
        }
    }

    float O[32];
#pragma unroll
    for (int i = 0; i < 32; i++) O[i] = 0.f;
    float l0 = 0.f, l1 = 0.f;

#pragma unroll 1
    for (int kt = 0; kt < 32; kt++) {
        if (kt == 31) { CP_WAIT0; } else { CP_WAIT1; }
        __syncthreads();
        const uint32_t kb = sb + SM_KB + (kt & 1) * 16384;

        // ---- MMA1: S = Qhi*Khi^T + Qlo*Khi^T + Qhi*Klo^T
        float Sv[32];
#pragma unroll
        for (int i = 0; i < 32; i++) Sv[i] = 0.f;
        {
            int brow0 = (lane & 7) + ((lane >> 4) << 3);
#pragma unroll
            for (int ks = 0; ks < 4; ks++) {
                int c = 2 * ks + ((lane >> 3) & 1);
#pragma unroll
                for (int np = 0; np < 4; np++) {
                    int r = np * 16 + brow0;
                    uint32_t a = kb + r * 128 + ((c ^ (r & 7)) << 4);
                    uint32_t bhf[4], blf[4];
                    ldsm_x4(bhf, a);
                    ldsm_x4(blf, a + 8192);
                    mma_bf16(Sv + np * 8,     qh + ks * 4, bhf);
                    mma_bf16(Sv + np * 8 + 4, qh + ks * 4, bhf + 2);
                    mma_bf16(Sv + np * 8,     ql + ks * 4, bhf);
                    mma_bf16(Sv + np * 8 + 4, ql + ks * 4, bhf + 2);
                    mma_bf16(Sv + np * 8,     qh + ks * 4, blf);
                    mma_bf16(Sv + np * 8 + 4, qh + ks * 4, blf + 2);
                }
            }
        }

        // ---- softmax (bounded: |s|<=64 -> exp arg in [-8,8], no max needed)
        float ps0 = 0.f, ps1 = 0.f;
#pragma unroll
        for (int j = 0; j < 8; j++) {
            float p0 = ex2f(Sv[j * 4 + 0] * SCL);
            float p1 = ex2f(Sv[j * 4 + 1] * SCL);
            float p2 = ex2f(Sv[j * 4 + 2] * SCL);
            float p3 = ex2f(Sv[j * 4 + 3] * SCL);
            Sv[j * 4 + 0] = p0; Sv[j * 4 + 1] = p1;
            Sv[j * 4 + 2] = p2; Sv[j * 4 + 3] = p3;
            ps0 += p0 + p1; ps1 += p2 + p3;
        }
        ps0 += __shfl_xor_sync(0xffffffffu, ps0, 1);
        ps0 += __shfl_xor_sync(0xffffffffu, ps0, 2);
        ps1 += __shfl_xor_sync(0xffffffffu, ps1, 1);
        ps1 += __shfl_xor_sync(0xffffffffu, ps1, 2);
        l0 += ps0; l1 += ps1;

        // ---- P -> bf16 hi/lo A-fragments (register-only, MMA1 D layout == MMA2 A layout)
        uint32_t ph[16], pl[16];
#pragma unroll
        for (int ks = 0; ks < 4; ks++) {
            split2(Sv[(2 * ks) * 4 + 0], Sv[(2 * ks) * 4 + 1], ph[ks * 4 + 0], pl[ks * 4 + 0]);
            split2(Sv[(2 * ks) * 4 + 2], Sv[(2 * ks) * 4 + 3], ph[ks * 4 + 1], pl[ks * 4 + 1]);
            split2(Sv[(2 * ks + 1) * 4 + 0], Sv[(2 * ks + 1) * 4 + 1], ph[ks * 4 + 2], pl[ks * 4 + 2]);
            split2(Sv[(2 * ks + 1) * 4 + 2], Sv[(2 * ks + 1) * 4 + 3], ph[ks * 4 + 3], pl[ks * 4 + 3]);
        }

        // ---- MMA2: O += Phi*Vhi + Plo*Vhi + Phi*Vlo   (V tile == K tile)
        {
#pragma unroll
            for (int ks = 0; ks < 4; ks++) {
                int vrow = 16 * ks + (lane & 7) + (((lane >> 3) & 1) << 3);
#pragma unroll
                for (int np = 0; np < 4; np++) {
                    int c = np * 2 + (lane >> 4);
                    uint32_t a = kb + vrow * 128 + ((c ^ (vrow & 7)) << 4);
                    uint32_t vh[4], vl[4];
                    ldsm_x4_t(vh, a);
                    ldsm_x4_t(vl, a + 8192);
                    mma_bf16(O + np * 8,     ph + ks * 4, vh);
                    mma_bf16(O + np * 8 + 4, ph + ks * 4, vh + 2);
                    mma_bf16(O + np * 8,     pl + ks * 4, vh);
                    mma_bf16(O + np * 8 + 4, pl + ks * 4, vh + 2);
                    mma_bf16(O + np * 8,     ph + ks * 4, vl);
                    mma_bf16(O + np * 8 + 4, ph + ks * 4, vl + 2);
                }
            }
        }

        __syncthreads();     // all warps done with buf (kt&1) before overwrite
        if (kt + 2 < 32) {
            uint32_t nb = sb + SM_KB + (kt & 1) * 16384;
            cpa_tile(nb,        Ahi + (kt + 2) * 64 * 64, 64, 64, tid);
            cpa_tile(nb + 8192, Alo + (kt + 2) * 64 * 64, 64, 64, tid);
            CP_COMMIT;
        }
    }

    // ---- normalize + write AO as bf16 hi/lo (layout [b][s][e], e = h*64+d)
    float inv0 = 1.f / l0, inv1 = 1.f / l1;
    int r0 = qt * 128 + 16 * w + (lane >> 2);
    int colb = h * 64 + 2 * (lane & 3);
#pragma unroll
    for (int j = 0; j < 8; j++) {
        int col = colb + j * 8;
        size_t i0 = (size_t)(b * Sc + r0) * Ec + col;
        uint32_t hp, lp;
        split2(O[j * 4 + 0] * inv0, O[j * 4 + 1] * inv0, hp, lp);
        *reinterpret_cast<uint32_t*>(&g_AOhi[i0]) = hp;
        *reinterpret_cast<uint32_t*>(&g_AOlo[i0]) = lp;
        split2(O[j * 4 + 2] * inv1, O[j * 4 + 3] * inv1, hp, lp);
        *reinterpret_cast<uint32_t*>(&g_AOhi[i0 + 8 * Ec]) = hp;
        *reinterpret_cast<uint32_t*>(&g_AOlo[i0 + 8 * Ec]) = lp;
    }
}

// ---------------------------------------------------------------------------
// Kernel 4: epilogue GEMM out = AO @ W^T + b via mma.sync, bf16 3-term
// CTA: 128m x 64n, K chunks of 64, double-buffered cp.async.
// ---------------------------------------------------------------------------
constexpr int GB = 49152;              // per-buffer: AHI 16K | ALO 16K | WHI 8K | WLO 8K
constexpr int GEMM_SMEM = 2 * GB;

__global__ void __launch_bounds__(256) gemm_mma_kernel(const float* __restrict__ bias,
                                                       float* __restrict__ out) {
    extern __shared__ char smem[];
    const uint32_t sb = smem_u32(smem);
    const int tid = threadIdx.x, lane = tid & 31, w = tid >> 5;
    const int n0 = blockIdx.x * 64, m0 = blockIdx.y * 128;

    for (int c = 0; c < 2; c++) {
        uint32_t base = sb + c * GB;
        cpa_tile(base,         g_AOhi + (size_t)m0 * Ec + c * 64, 128, Ec, tid);
        cpa_tile(base + 16384, g_AOlo + (size_t)m0 * Ec + c * 64, 128, Ec, tid);
        cpa_tile(base + 32768, g_Whi  + (size_t)n0 * Ec + c * 64,  64, Ec, tid);
        cpa_tile(base + 40960, g_Wlo  + (size_t)n0 * Ec + c * 64,  64, Ec, tid);
        CP_COMMIT;
    }

    float O[32];
#pragma unroll
    for (int i = 0; i < 32; i++) O[i] = 0.f;

#pragma unroll 1
    for (int ch = 0; ch < 8; ch++) {
        if (ch == 7) { CP_WAIT0; } else { CP_WAIT1; }
        __syncthreads();
        uint32_t base = sb + (ch & 1) * GB;

        uint32_t ah[16], al[16];
        int arow = 16 * w + (lane & 7) + (((lane >> 3) & 1) << 3);
#pragma unroll
        for (int ks = 0; ks < 4; ks++) {
            int c = 2 * ks + (lane >> 4);
            uint32_t a = base + arow * 128 + ((c ^ (arow & 7)) << 4);
            ldsm_x4(ah + ks * 4, a);
            ldsm_x4(al + ks * 4, a + 16384);
        }
        int brow0 = (lane & 7) + ((lane >> 4) << 3);
#pragma unroll
        for (int ks = 0; ks < 4; ks++) {
            int c = 2 * ks + ((lane >> 3) & 1);
#pragma unroll
            for (int np = 0; np < 4; np++) {
                int r = np * 16 + brow0;
                uint32_t a = base + 32768 + r * 128 + ((c ^ (r & 7)) << 4);
                uint32_t bhf[4], blf[4];
                ldsm_x4(bhf, a);
                ldsm_x4(blf, a + 8192);
                mma_bf16(O + np * 8,     ah + ks * 4, bhf);
                mma_bf16(O + np * 8 + 4, ah + ks * 4, bhf + 2);
                mma_bf16(O + np * 8,     al + ks * 4, bhf);
                mma_bf16(O + np * 8 + 4, al + ks * 4, bhf + 2);
                mma_bf16(O + np * 8,     ah + ks * 4, blf);
                mma_bf16(O + np * 8 + 4, ah + ks * 4, blf + 2);
            }
        }
        __syncthreads();
        if (ch + 2 < 8) {
            uint32_t nb2 = sb + (ch & 1) * GB;
            int c2 = ch + 2;
            cpa_tile(nb2,         g_AOhi + (size_t)m0 * Ec + c2 * 64, 128, Ec, tid);
            cpa_tile(nb2 + 16384, g_AOlo + (size_t)m0 * Ec + c2 * 64, 128, Ec, tid);
            cpa_tile(nb2 + 32768, g_Whi  + (size_t)n0 * Ec + c2 * 64,  64, Ec, tid);
            cpa_tile(nb2 + 40960, g_Wlo  + (size_t)n0 * Ec + c2 * 64,  64, Ec, tid);
            CP_COMMIT;
        }
    }

    int m = m0 + 16 * w + (lane >> 2);
    int nb = n0 + 2 * (lane & 3);
#pragma unroll
    for (int j = 0; j < 8; j++) {
        int n = nb + j * 8;
        float b0 = bias[n], b1 = bias[n + 1];
        *reinterpret_cast<float2*>(&out[(size_t)m * Ec + n]) =
            make_float2(O[j * 4 + 0] + b0, O[j * 4 + 1] + b1);
        *reinterpret_cast<float2*>(&out[(size_t)(m + 8) * Ec + n]) =
            make_float2(O[j * 4 + 2] + b0, O[j * 4 + 3] + b1);
    }
}

// ---------------------------------------------------------------------------
extern "C" void kernel_launch(void* const* d_in, const int* in_sizes, int n_in,
                              void* d_out, int out_size) {
    const float* x     = (const float*)d_in[0];
    const float* theta = (const float*)d_in[1];
    const float* W     = (const float*)d_in[2];
    const float* bias  = (const float*)d_in[3];
    float* out = (float*)d_out;

    cudaFuncSetAttribute(flash_mma_kernel, cudaFuncAttributeMaxDynamicSharedMemorySize, FL_SMEM);
    cudaFuncSetAttribute(gemm_mma_kernel, cudaFuncAttributeMaxDynamicSharedMemorySize, GEMM_SMEM);

    cos_split_kernel<<<(Bc * Sc * Ec / 4) / 256, 256>>>(x, theta);
    w_split_kernel<<<(Ec * Ec / 4) / 256, 256>>>(W);

    dim3 fgrid(Sc / 128, Hc, Bc);
    flash_mma_kernel<<<fgrid, 256, FL_SMEM>>>();

    dim3 ggrid(Ec / 64, (Bc * Sc) / 128);
    gemm_mma_kernel<<<ggrid, 256, GEMM_SMEM>>>(bias, out);
}

// round 5
// speedup vs baseline: 7.4138x; 2.0995x over previous
#include <cuda_runtime.h>
#include <cuda_bf16.h>
#include <cuda_fp16.h>
#include <cstdint>

constexpr int Bc = 4, Sc = 2048, Ec = 512, Hc = 8, DKc = 64;

__device__ __align__(256) __half         g_Af  [Bc * Hc * Sc * DKc];  // fp16 cos(x+theta)
__device__ __align__(256) __nv_bfloat16  g_AOhi[Bc * Sc * Ec];
__device__ __align__(256) __nv_bfloat16  g_AOlo[Bc * Sc * Ec];
__device__ __align__(256) __nv_bfloat16  g_Whi [Ec * Ec];
__device__ __align__(256) __nv_bfloat16  g_Wlo [Ec * Ec];

// ---------------------------------------------------------------------------
// helpers
// ---------------------------------------------------------------------------
__device__ __forceinline__ uint32_t smem_u32(const void* p) {
    uint32_t a;
    asm("{ .reg .u64 t; cvta.to.shared.u64 t, %1; cvt.u32.u64 %0, t; }" : "=r"(a) : "l"(p));
    return a;
}
__device__ __forceinline__ void ldsm_x4(uint32_t* r, uint32_t addr) {
    asm volatile("ldmatrix.sync.aligned.m8n8.x4.shared.b16 {%0,%1,%2,%3}, [%4];"
                 : "=r"(r[0]), "=r"(r[1]), "=r"(r[2]), "=r"(r[3]) : "r"(addr));
}
__device__ __forceinline__ void ldsm_x4_t(uint32_t* r, uint32_t addr) {
    asm volatile("ldmatrix.sync.aligned.m8n8.x4.trans.shared.b16 {%0,%1,%2,%3}, [%4];"
                 : "=r"(r[0]), "=r"(r[1]), "=r"(r[2]), "=r"(r[3]) : "r"(addr));
}
__device__ __forceinline__ void mma_bf16(float* d, const uint32_t* a, const uint32_t* b) {
    asm volatile("mma.sync.aligned.m16n8k16.row.col.f32.bf16.bf16.f32 "
                 "{%0,%1,%2,%3}, {%4,%5,%6,%7}, {%8,%9}, {%0,%1,%2,%3};"
                 : "+f"(d[0]), "+f"(d[1]), "+f"(d[2]), "+f"(d[3])
                 : "r"(a[0]), "r"(a[1]), "r"(a[2]), "r"(a[3]), "r"(b[0]), "r"(b[1]));
}
__device__ __forceinline__ void mma_f16(float* d, const uint32_t* a, const uint32_t* b) {
    asm volatile("mma.sync.aligned.m16n8k16.row.col.f32.f16.f16.f32 "
                 "{%0,%1,%2,%3}, {%4,%5,%6,%7}, {%8,%9}, {%0,%1,%2,%3};"
                 : "+f"(d[0]), "+f"(d[1]), "+f"(d[2]), "+f"(d[3])
                 : "r"(a[0]), "r"(a[1]), "r"(a[2]), "r"(a[3]), "r"(b[0]), "r"(b[1]));
}
__device__ __forceinline__ float ex2f(float x) {
    float y; asm("ex2.approx.f32 %0, %1;" : "=f"(y) : "f"(x)); return y;
}
__device__ __forceinline__ uint32_t packh2(float x0, float x1) {  // lo=x0, hi=x1
    uint32_t p; asm("cvt.rn.f16x2.f32 %0, %1, %2;" : "=r"(p) : "f"(x1), "f"(x0));
    return p;
}
// bf16 hi/lo split for the 3-term epilogue
__device__ __forceinline__ void split2(float x0, float x1, uint32_t& hp, uint32_t& lp) {
    uint32_t u0 = __float_as_uint(x0) & 0xffff0000u;
    uint32_t u1 = __float_as_uint(x1) & 0xffff0000u;
    hp = u1 | (u0 >> 16);
    float r0 = x0 - __uint_as_float(u0);
    float r1 = x1 - __uint_as_float(u1);
    asm("cvt.rn.bf16x2.f32 %0, %1, %2;" : "=r"(lp) : "f"(r1), "f"(r0));
}

#define CP_COMMIT asm volatile("cp.async.commit_group;" ::: "memory")
#define CP_WAIT0  asm volatile("cp.async.wait_group 0;" ::: "memory")
#define CP_WAIT1  asm volatile("cp.async.wait_group 1;" ::: "memory")
#define CP_WAIT2  asm volatile("cp.async.wait_group 2;" ::: "memory")

// copy rows x 128B tile (64 fp16/bf16 elems per row) gmem -> swizzled smem
template <typename T>
__device__ __forceinline__ void cpa_tile(uint32_t sdst, const T* g,
                                         int rows, int stride, int tid) {
    int n = rows * 8;
    for (int idx = tid; idx < n; idx += 256) {
        int r = idx >> 3, c = idx & 7;
        uint32_t d = sdst + r * 128 + ((c ^ (r & 7)) << 4);
        const T* s = g + (size_t)r * stride + c * 8;
        asm volatile("cp.async.cg.shared.global [%0], [%1], 16;" :: "r"(d), "l"(s));
    }
}

constexpr float SCL = 0.18033688011112042f;  // log2(e)/8

// ---------------------------------------------------------------------------
// Kernel 1: A = fp16(cos(x+theta)), head-major layout
// ---------------------------------------------------------------------------
__global__ __launch_bounds__(256) void cos_kernel(const float* __restrict__ x,
                                                  const float* __restrict__ theta) {
    int t = blockIdx.x * 256 + threadIdx.x;
    int base = t * 4;
    int e = base & (Ec - 1), bs = base >> 9;
    int d = e & (DKc - 1), h = e >> 6;
    int b = bs >> 11, s = bs & (Sc - 1);

    float4 xv = *reinterpret_cast<const float4*>(x + base);
    float4 tv = *reinterpret_cast<const float4*>(theta + d);
    float c0 = cosf(xv.x + tv.x), c1 = cosf(xv.y + tv.y);
    float c2 = cosf(xv.z + tv.z), c3 = cosf(xv.w + tv.w);

    size_t o = (((size_t)(b * Hc + h) * Sc) + s) * DKc + d;
    *reinterpret_cast<uint2*>(&g_Af[o]) = make_uint2(packh2(c0, c1), packh2(c2, c3));
}

// ---------------------------------------------------------------------------
// Kernel 2: W bf16 hi/lo split (for the 3-term epilogue)
// ---------------------------------------------------------------------------
__global__ __launch_bounds__(256) void w_split_kernel(const float* __restrict__ W) {
    int base = (blockIdx.x * 256 + threadIdx.x) * 4;
    float4 wv = *reinterpret_cast<const float4*>(W + base);
    uint32_t hp0, lp0, hp1, lp1;
    split2(wv.x, wv.y, hp0, lp0);
    split2(wv.z, wv.w, hp1, lp1);
    *reinterpret_cast<uint2*>(&g_Whi[base]) = make_uint2(hp0, hp1);
    *reinterpret_cast<uint2*>(&g_Wlo[base]) = make_uint2(lp0, lp1);
}

// ---------------------------------------------------------------------------
// Kernel 3: flash attention, fp16 single-term mma.sync, bounded softmax
// SMEM: Q 16KB | 3 x 8KB K buffers = 40960 B
// ---------------------------------------------------------------------------
constexpr int SM_KB   = 16384;
constexpr int KBUF    = 8192;
constexpr int FL_SMEM = SM_KB + 3 * KBUF;

__global__ void __launch_bounds__(256, 2) flash_mma_kernel() {
    extern __shared__ char smem[];
    const uint32_t sb = smem_u32(smem);
    const int tid = threadIdx.x, lane = tid & 31, w = tid >> 5;
    const int qt = blockIdx.x, h = blockIdx.y, b = blockIdx.z;
    const __half* Af = g_Af + (size_t)(b * Hc + h) * Sc * DKc;

    // prologue: Q (group 0), K0 (g1), K1 (g2)
    cpa_tile(sb, Af + qt * 128 * 64, 128, 64, tid);
    CP_COMMIT;
    cpa_tile(sb + SM_KB, Af, 64, 64, tid);
    CP_COMMIT;
    cpa_tile(sb + SM_KB + KBUF, Af + 64 * 64, 64, 64, tid);
    CP_COMMIT;
    CP_WAIT2;                    // Q landed
    __syncthreads();

    // Q fragments (persist)
    uint32_t qf[16];
    {
        int row = 16 * w + (lane & 7) + (((lane >> 3) & 1) << 3);
#pragma unroll
        for (int ks = 0; ks < 4; ks++) {
            int c = 2 * ks + (lane >> 4);
            ldsm_x4(qf + ks * 4, sb + row * 128 + ((c ^ (row & 7)) << 4));
        }
    }

    float O[32];
#pragma unroll
    for (int i = 0; i < 32; i++) O[i] = 0.f;
    float l0 = 0.f, l1 = 0.f;

    const int brow0 = (lane & 7) + ((lane >> 4) << 3);

#pragma unroll 1
    for (int kt = 0; kt < 32; kt++) {
        if (kt == 31) { CP_WAIT0; } else { CP_WAIT1; }
        __syncthreads();
        // prefetch kt+2 into buf (kt+2)%3 (that buf was consumed in iter kt-1;
        // the barrier above guarantees every warp has left iter kt-1)
        if (kt + 2 < 32) {
            cpa_tile(sb + SM_KB + ((kt + 2) % 3) * KBUF, Af + (kt + 2) * 64 * 64, 64, 64, tid);
            CP_COMMIT;
        }
        const uint32_t kb = sb + SM_KB + (kt % 3) * KBUF;

        // ---- MMA1: S = Q K^T (single fp16 pass)
        float Sv[32];
#pragma unroll
        for (int i = 0; i < 32; i++) Sv[i] = 0.f;
#pragma unroll
        for (int ks = 0; ks < 4; ks++) {
            int c = 2 * ks + ((lane >> 3) & 1);
#pragma unroll
            for (int np = 0; np < 4; np++) {
                int r = np * 16 + brow0;
                uint32_t bf[4];
                ldsm_x4(bf, kb + r * 128 + ((c ^ (r & 7)) << 4));
                mma_f16(Sv + np * 8,     qf + ks * 4, bf);
                mma_f16(Sv + np * 8 + 4, qf + ks * 4, bf + 2);
            }
        }

        // ---- softmax (bounded: exp arg in [-8,8], no running max)
        float ps0 = 0.f, ps1 = 0.f;
#pragma unroll
        for (int j = 0; j < 8; j++) {
            float p0 = ex2f(Sv[j * 4 + 0] * SCL);
            float p1 = ex2f(Sv[j * 4 + 1] * SCL);
            float p2 = ex2f(Sv[j * 4 + 2] * SCL);
            float p3 = ex2f(Sv[j * 4 + 3] * SCL);
            Sv[j * 4 + 0] = p0; Sv[j * 4 + 1] = p1;
            Sv[j * 4 + 2] = p2; Sv[j * 4 + 3] = p3;
            ps0 += p0 + p1; ps1 += p2 + p3;
        }
        ps0 += __shfl_xor_sync(0xffffffffu, ps0, 1);
        ps0 += __shfl_xor_sync(0xffffffffu, ps0, 2);
        ps1 += __shfl_xor_sync(0xffffffffu, ps1, 1);
        ps1 += __shfl_xor_sync(0xffffffffu, ps1, 2);
        l0 += ps0; l1 += ps1;

        // ---- P -> fp16 A-fragments (MMA1 D layout == MMA2 A layout)
        uint32_t pf[16];
#pragma unroll
        for (int ks = 0; ks < 4; ks++) {
            pf[ks * 4 + 0] = packh2(Sv[(2 * ks) * 4 + 0], Sv[(2 * ks) * 4 + 1]);
            pf[ks * 4 + 1] = packh2(Sv[(2 * ks) * 4 + 2], Sv[(2 * ks) * 4 + 3]);
            pf[ks * 4 + 2] = packh2(Sv[(2 * ks + 1) * 4 + 0], Sv[(2 * ks + 1) * 4 + 1]);
            pf[ks * 4 + 3] = packh2(Sv[(2 * ks + 1) * 4 + 2], Sv[(2 * ks + 1) * 4 + 3]);
        }

        // ---- MMA2: O += P V   (V tile == K tile)
#pragma unroll
        for (int ks = 0; ks < 4; ks++) {
            int vrow = 16 * ks + (lane & 7) + (((lane >> 3) & 1) << 3);
#pragma unroll
            for (int np = 0; np < 4; np++) {
                int c = np * 2 + (lane >> 4);
                uint32_t vf[4];
                ldsm_x4_t(vf, kb + vrow * 128 + ((c ^ (vrow & 7)) << 4));
                mma_f16(O + np * 8,     pf + ks * 4, vf);
                mma_f16(O + np * 8 + 4, pf + ks * 4, vf + 2);
            }
        }
    }

    // ---- normalize + write AO as bf16 hi/lo ([b][s][e], e = h*64+d)
    float inv0 = 1.f / l0, inv1 = 1.f / l1;
    int r0 = qt * 128 + 16 * w + (lane >> 2);
    int colb = h * 64 + 2 * (lane & 3);
#pragma unroll
    for (int j = 0; j < 8; j++) {
        int col = colb + j * 8;
        size_t i0 = (size_t)(b * Sc + r0) * Ec + col;
        uint32_t hp, lp;
        split2(O[j * 4 + 0] * inv0, O[j * 4 + 1] * inv0, hp, lp);
        *reinterpret_cast<uint32_t*>(&g_AOhi[i0]) = hp;
        *reinterpret_cast<uint32_t*>(&g_AOlo[i0]) = lp;
        split2(O[j * 4 + 2] * inv1, O[j * 4 + 3] * inv1, hp, lp);
        *reinterpret_cast<uint32_t*>(&g_AOhi[i0 + 8 * Ec]) = hp;
        *reinterpret_cast<uint32_t*>(&g_AOlo[i0 + 8 * Ec]) = lp;
    }
}

// ---------------------------------------------------------------------------
// Kernel 4: epilogue GEMM out = AO @ W^T + b, bf16 3-term
// ---------------------------------------------------------------------------
constexpr int GB = 49152;
constexpr int GEMM_SMEM = 2 * GB;

__global__ void __launch_bounds__(256) gemm_mma_kernel(const float* __restrict__ bias,
                                                       float* __restrict__ out) {
    extern __shared__ char smem[];
    const uint32_t sb = smem_u32(smem);
    const int tid = threadIdx.x, lane = tid & 31, w = tid >> 5;
    const int n0 = blockIdx.x * 64, m0 = blockIdx.y * 128;

    for (int c = 0; c < 2; c++) {
        uint32_t base = sb + c * GB;
        cpa_tile(base,         g_AOhi + (size_t)m0 * Ec + c * 64, 128, Ec, tid);
        cpa_tile(base + 16384, g_AOlo + (size_t)m0 * Ec + c * 64, 128, Ec, tid);
        cpa_tile(base + 32768, g_Whi  + (size_t)n0 * Ec + c * 64,  64, Ec, tid);
        cpa_tile(base + 40960, g_Wlo  + (size_t)n0 * Ec + c * 64,  64, Ec, tid);
        CP_COMMIT;
    }

    float O[32];
#pragma unroll
    for (int i = 0; i < 32; i++) O[i] = 0.f;

#pragma unroll 1
    for (int ch = 0; ch < 8; ch++) {
        if (ch == 7) { CP_WAIT0; } else { CP_WAIT1; }
        __syncthreads();
        uint32_t base = sb + (ch & 1) * GB;

        uint32_t ah[16], al[16];
        int arow = 16 * w + (lane & 7) + (((lane >> 3) & 1) << 3);
#pragma unroll
        for (int ks = 0; ks < 4; ks++) {
            int c = 2 * ks + (lane >> 4);
            uint32_t a = base + arow * 128 + ((c ^ (arow & 7)) << 4);
            ldsm_x4(ah + ks * 4, a);
            ldsm_x4(al + ks * 4, a + 16384);
        }
        int brow0 = (lane & 7) + ((lane >> 4) << 3);
#pragma unroll
        for (int ks = 0; ks < 4; ks++) {
            int c = 2 * ks + ((lane >> 3) & 1);
#pragma unroll
            for (int np = 0; np < 4; np++) {
                int r = np * 16 + brow0;
                uint32_t a = base + 32768 + r * 128 + ((c ^ (r & 7)) << 4);
                uint32_t bhf[4], blf[4];
                ldsm_x4(bhf, a);
                ldsm_x4(blf, a + 8192);
                mma_bf16(O + np * 8,     ah + ks * 4, bhf);
                mma_bf16(O + np * 8 + 4, ah + ks * 4, bhf + 2);
                mma_bf16(O + np * 8,     al + ks * 4, bhf);
                mma_bf16(O + np * 8 + 4, al + ks * 4, bhf + 2);
                mma_bf16(O + np * 8,     ah + ks * 4, blf);
                mma_bf16(O + np * 8 + 4, ah + ks * 4, blf + 2);
            }
        }
        __syncthreads();
        if (ch + 2 < 8) {
            uint32_t nb2 = sb + (ch & 1) * GB;
            int c2 = ch + 2;
            cpa_tile(nb2,         g_AOhi + (size_t)m0 * Ec + c2 * 64, 128, Ec, tid);
            cpa_tile(nb2 + 16384, g_AOlo + (size_t)m0 * Ec + c2 * 64, 128, Ec, tid);
            cpa_tile(nb2 + 32768, g_Whi  + (size_t)n0 * Ec + c2 * 64,  64, Ec, tid);
            cpa_tile(nb2 + 40960, g_Wlo  + (size_t)n0 * Ec + c2 * 64,  64, Ec, tid);
            CP_COMMIT;
        }
    }

    int m = m0 + 16 * w + (lane >> 2);
    int nb = n0 + 2 * (lane & 3);
#pragma unroll
    for (int j = 0; j < 8; j++) {
        int n = nb + j * 8;
        float b0 = bias[n], b1 = bias[n + 1];
        *reinterpret_cast<float2*>(&out[(size_t)m * Ec + n]) =
            make_float2(O[j * 4 + 0] + b0, O[j * 4 + 1] + b1);
        *reinterpret_cast<float2*>(&out[(size_t)(m + 8) * Ec + n]) =
            make_float2(O[j * 4 + 2] + b0, O[j * 4 + 3] + b1);
    }
}

// ---------------------------------------------------------------------------
extern "C" void kernel_launch(void* const* d_in, const int* in_sizes, int n_in,
                              void* d_out, int out_size) {
    const float* x     = (const float*)d_in[0];
    const float* theta = (const float*)d_in[1];
    const float* W     = (const float*)d_in[2];
    const float* bias  = (const float*)d_in[3];
    float* out = (float*)d_out;

    cudaFuncSetAttribute(flash_mma_kernel, cudaFuncAttributeMaxDynamicSharedMemorySize, FL_SMEM);
    cudaFuncSetAttribute(gemm_mma_kernel, cudaFuncAttributeMaxDynamicSharedMemorySize, GEMM_SMEM);

    cos_kernel<<<(Bc * Sc * Ec / 4) / 256, 256>>>(x, theta);
    w_split_kernel<<<(Ec * Ec / 4) / 256, 256>>>(W);

    dim3 fgrid(Sc / 128, Hc, Bc);
    flash_mma_kernel<<<fgrid, 256, FL_SMEM>>>();

    dim3 ggrid(Ec / 64, (Bc * Sc) / 128);
    gemm_mma_kernel<<<ggrid, 256, GEMM_SMEM>>>(bias, out);
}

// round 6
// speedup vs baseline: 8.6268x; 1.1636x over previous
#include <cuda_runtime.h>
#include <cuda_bf16.h>
#include <cuda_fp16.h>
#include <cstdint>

constexpr int Bc = 4, Sc = 2048, Ec = 512, Hc = 8, DKc = 64;

__device__ __align__(256) __half g_Af  [Bc * Hc * Sc * DKc];  // fp16 cos(x+theta), head-major
__device__ __align__(256) __half g_AOf [Bc * Sc * Ec];        // attention out, fp16
__device__ __align__(256) __half g_Whif[Ec * Ec];             // W fp16 hi
__device__ __align__(256) __half g_Wlof[Ec * Ec];             // W fp16 lo (residual)

// ---------------------------------------------------------------------------
// helpers
// ---------------------------------------------------------------------------
__device__ __forceinline__ uint32_t smem_u32(const void* p) {
    uint32_t a;
    asm("{ .reg .u64 t; cvta.to.shared.u64 t, %1; cvt.u32.u64 %0, t; }" : "=r"(a) : "l"(p));
    return a;
}
__device__ __forceinline__ void ldsm_x4(uint32_t* r, uint32_t addr) {
    asm volatile("ldmatrix.sync.aligned.m8n8.x4.shared.b16 {%0,%1,%2,%3}, [%4];"
                 : "=r"(r[0]), "=r"(r[1]), "=r"(r[2]), "=r"(r[3]) : "r"(addr));
}
__device__ __forceinline__ void ldsm_x4_t(uint32_t* r, uint32_t addr) {
    asm volatile("ldmatrix.sync.aligned.m8n8.x4.trans.shared.b16 {%0,%1,%2,%3}, [%4];"
                 : "=r"(r[0]), "=r"(r[1]), "=r"(r[2]), "=r"(r[3]) : "r"(addr));
}
__device__ __forceinline__ void mma_f16(float* d, const uint32_t* a, const uint32_t* b) {
    asm volatile("mma.sync.aligned.m16n8k16.row.col.f32.f16.f16.f32 "
                 "{%0,%1,%2,%3}, {%4,%5,%6,%7}, {%8,%9}, {%0,%1,%2,%3};"
                 : "+f"(d[0]), "+f"(d[1]), "+f"(d[2]), "+f"(d[3])
                 : "r"(a[0]), "r"(a[1]), "r"(a[2]), "r"(a[3]), "r"(b[0]), "r"(b[1]));
}
__device__ __forceinline__ uint32_t packh2(float x0, float x1) {  // lo=x0, hi=x1
    uint32_t p; asm("cvt.rn.f16x2.f32 %0, %1, %2;" : "=r"(p) : "f"(x1), "f"(x0));
    return p;
}
__device__ __forceinline__ uint32_t hmul2(uint32_t a, uint32_t b) {
    uint32_t d; asm("mul.rn.f16x2 %0, %1, %2;" : "=r"(d) : "r"(a), "r"(b)); return d;
}
__device__ __forceinline__ uint32_t hadd2(uint32_t a, uint32_t b) {
    uint32_t d; asm("add.rn.f16x2 %0, %1, %2;" : "=r"(d) : "r"(a), "r"(b)); return d;
}
__device__ __forceinline__ uint32_t ex2h2(uint32_t a) {
    uint32_t d; asm("ex2.approx.f16x2 %0, %1;" : "=r"(d) : "r"(a)); return d;
}
__device__ __forceinline__ float h2sumf(uint32_t h) {   // float(lo) + float(hi)
    float a, b;
    asm("{ .reg .b16 l, u; mov.b32 {l, u}, %2; cvt.f32.f16 %0, l; cvt.f32.f16 %1, u; }"
        : "=f"(a), "=f"(b) : "r"(h));
    return a + b;
}

#define CP_COMMIT asm volatile("cp.async.commit_group;" ::: "memory")
#define CP_WAIT0  asm volatile("cp.async.wait_group 0;" ::: "memory")
#define CP_WAIT1  asm volatile("cp.async.wait_group 1;" ::: "memory")
#define CP_WAIT2  asm volatile("cp.async.wait_group 2;" ::: "memory")

// copy rows x 128B tile (64 fp16 per row) gmem -> swizzled smem
__device__ __forceinline__ void cpa_tile(uint32_t sdst, const __half* g,
                                         int rows, int stride, int tid) {
    int n = rows * 8;
    for (int idx = tid; idx < n; idx += 256) {
        int r = idx >> 3, c = idx & 7;
        uint32_t d = sdst + r * 128 + ((c ^ (r & 7)) << 4);
        const __half* s = g + (size_t)r * stride + c * 8;
        asm volatile("cp.async.cg.shared.global [%0], [%1], 16;" :: "r"(d), "l"(s));
    }
}

constexpr float SCL = 0.18033688011112042f;  // log2(e)/8

// ---------------------------------------------------------------------------
// Kernel 1: A = fp16(cos(x+theta)), head-major layout
// ---------------------------------------------------------------------------
__global__ __launch_bounds__(256) void cos_kernel(const float* __restrict__ x,
                                                  const float* __restrict__ theta) {
    int t = blockIdx.x * 256 + threadIdx.x;
    int base = t * 4;
    int e = base & (Ec - 1), bs = base >> 9;
    int d = e & (DKc - 1), h = e >> 6;
    int b = bs >> 11, s = bs & (Sc - 1);

    float4 xv = *reinterpret_cast<const float4*>(x + base);
    float4 tv = *reinterpret_cast<const float4*>(theta + d);
    float c0 = cosf(xv.x + tv.x), c1 = cosf(xv.y + tv.y);
    float c2 = cosf(xv.z + tv.z), c3 = cosf(xv.w + tv.w);

    size_t o = (((size_t)(b * Hc + h) * Sc) + s) * DKc + d;
    *reinterpret_cast<uint2*>(&g_Af[o]) = make_uint2(packh2(c0, c1), packh2(c2, c3));
}

// ---------------------------------------------------------------------------
// Kernel 2: W fp16 hi/lo split
// ---------------------------------------------------------------------------
__global__ __launch_bounds__(256) void w_split_kernel(const float* __restrict__ W) {
    int base = (blockIdx.x * 256 + threadIdx.x) * 4;
    float4 wv = *reinterpret_cast<const float4*>(W + base);
    float v[4] = { wv.x, wv.y, wv.z, wv.w };
    float hi[4], lo[4];
#pragma unroll
    for (int i = 0; i < 4; i++) {
        float h; asm("cvt.rn.f16.f32 %0, %1; cvt.f32.f16 %0, %0;" : "=f"(h) : "f"(v[i]));
        hi[i] = h; lo[i] = v[i] - h;
    }
    *reinterpret_cast<uint2*>(&g_Whif[base]) =
        make_uint2(packh2(hi[0], hi[1]), packh2(hi[2], hi[3]));
    *reinterpret_cast<uint2*>(&g_Wlof[base]) =
        make_uint2(packh2(lo[0], lo[1]), packh2(lo[2], lo[3]));
}

// ---------------------------------------------------------------------------
// Kernel 3: flash attention, fp16 mma.sync, f16x2 softmax (bounded, no max)
// SMEM: Q 16KB | 3 x 8KB K buffers = 40960 B
// ---------------------------------------------------------------------------
constexpr int SM_KB   = 16384;
constexpr int KBUF    = 8192;
constexpr int FL_SMEM = SM_KB + 3 * KBUF;

__global__ void __launch_bounds__(256, 2) flash_mma_kernel() {
    extern __shared__ char smem[];
    const uint32_t sb = smem_u32(smem);
    const int tid = threadIdx.x, lane = tid & 31, w = tid >> 5;
    const int qt = blockIdx.x, h = blockIdx.y, b = blockIdx.z;
    const __half* Af = g_Af + (size_t)(b * Hc + h) * Sc * DKc;

    cpa_tile(sb, Af + qt * 128 * 64, 128, 64, tid);
    CP_COMMIT;
    cpa_tile(sb + SM_KB, Af, 64, 64, tid);
    CP_COMMIT;
    cpa_tile(sb + SM_KB + KBUF, Af + 64 * 64, 64, 64, tid);
    CP_COMMIT;
    CP_WAIT2;                    // Q landed
    __syncthreads();

    // Q fragments (persist)
    uint32_t qf[16];
    {
        int row = 16 * w + (lane & 7) + (((lane >> 3) & 1) << 3);
#pragma unroll
        for (int ks = 0; ks < 4; ks++) {
            int c = 2 * ks + (lane >> 4);
            ldsm_x4(qf + ks * 4, sb + row * 128 + ((c ^ (row & 7)) << 4));
        }
    }

    float O[32];
#pragma unroll
    for (int i = 0; i < 32; i++) O[i] = 0.f;
    float l0 = 0.f, l1 = 0.f;

    const int brow0 = (lane & 7) + ((lane >> 4) << 3);
    const uint32_t SCL2 = packh2(SCL, SCL);

#pragma unroll 1
    for (int kt = 0; kt < 32; kt++) {
        if (kt == 31) { CP_WAIT0; } else { CP_WAIT1; }
        __syncthreads();
        if (kt + 2 < 32) {
            cpa_tile(sb + SM_KB + ((kt + 2) % 3) * KBUF, Af + (kt + 2) * 64 * 64, 64, 64, tid);
            CP_COMMIT;
        }
        const uint32_t kb = sb + SM_KB + (kt % 3) * KBUF;

        // ---- MMA1: S = Q K^T
        float Sv[32];
#pragma unroll
        for (int i = 0; i < 32; i++) Sv[i] = 0.f;
#pragma unroll
        for (int ks = 0; ks < 4; ks++) {
            int c = 2 * ks + ((lane >> 3) & 1);
#pragma unroll
            for (int np = 0; np < 4; np++) {
                int r = np * 16 + brow0;
                uint32_t bf[4];
                ldsm_x4(bf, kb + r * 128 + ((c ^ (r & 7)) << 4));
                mma_f16(Sv + np * 8,     qf + ks * 4, bf);
                mma_f16(Sv + np * 8 + 4, qf + ks * 4, bf + 2);
            }
        }

        // ---- softmax in f16x2: p = ex2(s * log2e/8); output IS the A-fragment
        uint32_t pA[8], pB[8];
#pragma unroll
        for (int j = 0; j < 8; j++) {
            pA[j] = ex2h2(hmul2(packh2(Sv[j * 4 + 0], Sv[j * 4 + 1]), SCL2));  // row r0
            pB[j] = ex2h2(hmul2(packh2(Sv[j * 4 + 2], Sv[j * 4 + 3]), SCL2));  // row r0+8
        }
        // l partial sums (HADD2 tree over positives, then fp32 accumulate)
        uint32_t tA = hadd2(hadd2(hadd2(pA[0], pA[1]), hadd2(pA[2], pA[3])),
                            hadd2(hadd2(pA[4], pA[5]), hadd2(pA[6], pA[7])));
        uint32_t tB = hadd2(hadd2(hadd2(pB[0], pB[1]), hadd2(pB[2], pB[3])),
                            hadd2(hadd2(pB[4], pB[5]), hadd2(pB[6], pB[7])));
        l0 += h2sumf(tA);
        l1 += h2sumf(tB);

        // ---- MMA2: O += P V (V tile == K tile); A-fragments from pA/pB
#pragma unroll
        for (int ks = 0; ks < 4; ks++) {
            uint32_t pf[4] = { pA[2 * ks], pB[2 * ks], pA[2 * ks + 1], pB[2 * ks + 1] };
            int vrow = 16 * ks + (lane & 7) + (((lane >> 3) & 1) << 3);
#pragma unroll
            for (int np = 0; np < 4; np++) {
                int c = np * 2 + (lane >> 4);
                uint32_t vf[4];
                ldsm_x4_t(vf, kb + vrow * 128 + ((c ^ (vrow & 7)) << 4));
                mma_f16(O + np * 8,     pf, vf);
                mma_f16(O + np * 8 + 4, pf, vf + 2);
            }
        }
    }

    // deferred cross-lane l reduction (cols split across lane groups of 4)
    l0 += __shfl_xor_sync(0xffffffffu, l0, 1);
    l0 += __shfl_xor_sync(0xffffffffu, l0, 2);
    l1 += __shfl_xor_sync(0xffffffffu, l1, 1);
    l1 += __shfl_xor_sync(0xffffffffu, l1, 2);

    // ---- normalize + write AO as single fp16 ([b][s][e], e = h*64+d)
    float inv0 = 1.f / l0, inv1 = 1.f / l1;
    int r0 = qt * 128 + 16 * w + (lane >> 2);
    int colb = h * 64 + 2 * (lane & 3);
#pragma unroll
    for (int j = 0; j < 8; j++) {
        int col = colb + j * 8;
        size_t i0 = (size_t)(b * Sc + r0) * Ec + col;
        *reinterpret_cast<uint32_t*>(&g_AOf[i0]) =
            packh2(O[j * 4 + 0] * inv0, O[j * 4 + 1] * inv0);
        *reinterpret_cast<uint32_t*>(&g_AOf[i0 + 8 * Ec]) =
            packh2(O[j * 4 + 2] * inv1, O[j * 4 + 3] * inv1);
    }
}

// ---------------------------------------------------------------------------
// Kernel 4: epilogue GEMM out = AO @ W^T + b, fp16 2-term (AO single, W hi/lo)
// per chunk buffer: AOf 16K | Whi 8K | Wlo 8K = 32K; double buffered
// ---------------------------------------------------------------------------
constexpr int GB = 32768;
constexpr int GEMM_SMEM = 2 * GB;

__global__ void __launch_bounds__(256, 3) gemm_mma_kernel(const float* __restrict__ bias,
                                                          float* __restrict__ out) {
    extern __shared__ char smem[];
    const uint32_t sb = smem_u32(smem);
    const int tid = threadIdx.x, lane = tid & 31, w = tid >> 5;
    const int n0 = blockIdx.x * 64, m0 = blockIdx.y * 128;

    for (int c = 0; c < 2; c++) {
        uint32_t base = sb + c * GB;
        cpa_tile(base,         g_AOf  + (size_t)m0 * Ec + c * 64, 128, Ec, tid);
        cpa_tile(base + 16384, g_Whif + (size_t)n0 * Ec + c * 64,  64, Ec, tid);
        cpa_tile(base + 24576, g_Wlof + (size_t)n0 * Ec + c * 64,  64, Ec, tid);
        CP_COMMIT;
    }

    float O[32];
#pragma unroll
    for (int i = 0; i < 32; i++) O[i] = 0.f;

#pragma unroll 1
    for (int ch = 0; ch < 8; ch++) {
        if (ch == 7) { CP_WAIT0; } else { CP_WAIT1; }
        __syncthreads();
        uint32_t base = sb + (ch & 1) * GB;

        uint32_t af[16];
        int arow = 16 * w + (lane & 7) + (((lane >> 3) & 1) << 3);
#pragma unroll
        for (int ks = 0; ks < 4; ks++) {
            int c = 2 * ks + (lane >> 4);
            ldsm_x4(af + ks * 4, base + arow * 128 + ((c ^ (arow & 7)) << 4));
        }
        int brow0 = (lane & 7) + ((lane >> 4) << 3);
#pragma unroll
        for (int ks = 0; ks < 4; ks++) {
            int c = 2 * ks + ((lane >> 3) & 1);
#pragma unroll
            for (int np = 0; np < 4; np++) {
                int r = np * 16 + brow0;
                uint32_t a = base + 16384 + r * 128 + ((c ^ (r & 7)) << 4);
                uint32_t bhf[4], blf[4];
                ldsm_x4(bhf, a);
                ldsm_x4(blf, a + 8192);
                mma_f16(O + np * 8,     af + ks * 4, bhf);
                mma_f16(O + np * 8 + 4, af + ks * 4, bhf + 2);
                mma_f16(O + np * 8,     af + ks * 4, blf);
                mma_f16(O + np * 8 + 4, af + ks * 4, blf + 2);
            }
        }
        __syncthreads();
        if (ch + 2 < 8) {
            uint32_t nb2 = sb + (ch & 1) * GB;
            int c2 = ch + 2;
            cpa_tile(nb2,         g_AOf  + (size_t)m0 * Ec + c2 * 64, 128, Ec, tid);
            cpa_tile(nb2 + 16384, g_Whif + (size_t)n0 * Ec + c2 * 64,  64, Ec, tid);
            cpa_tile(nb2 + 24576, g_Wlof + (size_t)n0 * Ec + c2 * 64,  64, Ec, tid);
            CP_COMMIT;
        }
    }

    int m = m0 + 16 * w + (lane >> 2);
    int nb = n0 + 2 * (lane & 3);
#pragma unroll
    for (int j = 0; j < 8; j++) {
        int n = nb + j * 8;
        float b0 = bias[n], b1 = bias[n + 1];
        *reinterpret_cast<float2*>(&out[(size_t)m * Ec + n]) =
            make_float2(O[j * 4 + 0] + b0, O[j * 4 + 1] + b1);
        *reinterpret_cast<float2*>(&out[(size_t)(m + 8) * Ec + n]) =
            make_float2(O[j * 4 + 2] + b0, O[j * 4 + 3] + b1);
    }
}

// ---------------------------------------------------------------------------
extern "C" void kernel_launch(void* const* d_in, const int* in_sizes, int n_in,
                              void* d_out, int out_size) {
    const float* x     = (const float*)d_in[0];
    const float* theta = (const float*)d_in[1];
    const float* W     = (const float*)d_in[2];
    const float* bias  = (const float*)d_in[3];
    float* out = (float*)d_out;

    cudaFuncSetAttribute(flash_mma_kernel, cudaFuncAttributeMaxDynamicSharedMemorySize, FL_SMEM);
    cudaFuncSetAttribute(gemm_mma_kernel, cudaFuncAttributeMaxDynamicSharedMemorySize, GEMM_SMEM);

    cos_kernel<<<(Bc * Sc * Ec / 4) / 256, 256>>>(x, theta);
    w_split_kernel<<<(Ec * Ec / 4) / 256, 256>>>(W);

    dim3 fgrid(Sc / 128, Hc, Bc);
    flash_mma_kernel<<<fgrid, 256, FL_SMEM>>>();

    dim3 ggrid(Ec / 64, (Bc * Sc) / 128);
    gemm_mma_kernel<<<ggrid, 256, GEMM_SMEM>>>(bias, out);
}

// round 7
// speedup vs baseline: 9.7099x; 1.1256x over previous
#include <cuda_runtime.h>
#include <cuda_fp16.h>
#include <cstdint>

constexpr int Bc = 4, Sc = 2048, Ec = 512, Hc = 8, DKc = 64;

__device__ __align__(256) __half g_Af [Bc * Hc * Sc * DKc];  // fp16 cos(x+theta), head-major
__device__ __align__(256) __half g_AOf[Bc * Sc * Ec];        // attention out, fp16
__device__ __align__(256) __half g_Wf [Ec * Ec];             // W fp16

// ---------------------------------------------------------------------------
// helpers
// ---------------------------------------------------------------------------
__device__ __forceinline__ uint32_t smem_u32(const void* p) {
    uint32_t a;
    asm("{ .reg .u64 t; cvta.to.shared.u64 t, %1; cvt.u32.u64 %0, t; }" : "=r"(a) : "l"(p));
    return a;
}
__device__ __forceinline__ void ldsm_x4(uint32_t* r, uint32_t addr) {
    asm volatile("ldmatrix.sync.aligned.m8n8.x4.shared.b16 {%0,%1,%2,%3}, [%4];"
                 : "=r"(r[0]), "=r"(r[1]), "=r"(r[2]), "=r"(r[3]) : "r"(addr));
}
__device__ __forceinline__ void ldsm_x4_t(uint32_t* r, uint32_t addr) {
    asm volatile("ldmatrix.sync.aligned.m8n8.x4.trans.shared.b16 {%0,%1,%2,%3}, [%4];"
                 : "=r"(r[0]), "=r"(r[1]), "=r"(r[2]), "=r"(r[3]) : "r"(addr));
}
__device__ __forceinline__ void mma_f16(float* d, const uint32_t* a, const uint32_t* b) {
    asm volatile("mma.sync.aligned.m16n8k16.row.col.f32.f16.f16.f32 "
                 "{%0,%1,%2,%3}, {%4,%5,%6,%7}, {%8,%9}, {%0,%1,%2,%3};"
                 : "+f"(d[0]), "+f"(d[1]), "+f"(d[2]), "+f"(d[3])
                 : "r"(a[0]), "r"(a[1]), "r"(a[2]), "r"(a[3]), "r"(b[0]), "r"(b[1]));
}
__device__ __forceinline__ uint32_t packh2(float x0, float x1) {  // lo=x0, hi=x1
    uint32_t p; asm("cvt.rn.f16x2.f32 %0, %1, %2;" : "=r"(p) : "f"(x1), "f"(x0));
    return p;
}
__device__ __forceinline__ uint32_t hmul2(uint32_t a, uint32_t b) {
    uint32_t d; asm("mul.rn.f16x2 %0, %1, %2;" : "=r"(d) : "r"(a), "r"(b)); return d;
}
__device__ __forceinline__ uint32_t hadd2(uint32_t a, uint32_t b) {
    uint32_t d; asm("add.rn.f16x2 %0, %1, %2;" : "=r"(d) : "r"(a), "r"(b)); return d;
}
__device__ __forceinline__ uint32_t ex2h2(uint32_t a) {
    uint32_t d; asm("ex2.approx.f16x2 %0, %1;" : "=r"(d) : "r"(a)); return d;
}
__device__ __forceinline__ float h2sumf(uint32_t h) {
    float a, b;
    asm("{ .reg .b16 l, u; mov.b32 {l, u}, %2; cvt.f32.f16 %0, l; cvt.f32.f16 %1, u; }"
        : "=f"(a), "=f"(b) : "r"(h));
    return a + b;
}

#define CP_COMMIT asm volatile("cp.async.commit_group;" ::: "memory")
#define CP_WAIT0  asm volatile("cp.async.wait_group 0;" ::: "memory")
#define CP_WAIT1  asm volatile("cp.async.wait_group 1;" ::: "memory")
#define CP_WAIT2  asm volatile("cp.async.wait_group 2;" ::: "memory")

// copy rows x 128B tile (64 fp16 per row) gmem -> swizzled smem
template <int NT>
__device__ __forceinline__ void cpa_tile(uint32_t sdst, const __half* g,
                                         int rows, int stride, int tid) {
    int n = rows * 8;
    for (int idx = tid; idx < n; idx += NT) {
        int r = idx >> 3, c = idx & 7;
        uint32_t d = sdst + r * 128 + ((c ^ (r & 7)) << 4);
        const __half* s = g + (size_t)r * stride + c * 8;
        asm volatile("cp.async.cg.shared.global [%0], [%1], 16;" :: "r"(d), "l"(s));
    }
}

constexpr float SCL = 0.18033688011112042f;  // log2(e)/8

// ---------------------------------------------------------------------------
// Kernel 1: A = fp16(cos(x+theta)), head-major layout
// ---------------------------------------------------------------------------
__global__ __launch_bounds__(256) void cos_kernel(const float* __restrict__ x,
                                                  const float* __restrict__ theta) {
    int t = blockIdx.x * 256 + threadIdx.x;
    int base = t * 4;
    int e = base & (Ec - 1), bs = base >> 9;
    int d = e & (DKc - 1), h = e >> 6;
    int b = bs >> 11, s = bs & (Sc - 1);

    float4 xv = *reinterpret_cast<const float4*>(x + base);
    float4 tv = *reinterpret_cast<const float4*>(theta + d);
    float c0 = cosf(xv.x + tv.x), c1 = cosf(xv.y + tv.y);
    float c2 = cosf(xv.z + tv.z), c3 = cosf(xv.w + tv.w);

    size_t o = (((size_t)(b * Hc + h) * Sc) + s) * DKc + d;
    *reinterpret_cast<uint2*>(&g_Af[o]) = make_uint2(packh2(c0, c1), packh2(c2, c3));
}

// ---------------------------------------------------------------------------
// Kernel 2: W -> fp16
// ---------------------------------------------------------------------------
__global__ __launch_bounds__(256) void w_half_kernel(const float* __restrict__ W) {
    int base = (blockIdx.x * 256 + threadIdx.x) * 4;
    float4 wv = *reinterpret_cast<const float4*>(W + base);
    *reinterpret_cast<uint2*>(&g_Wf[base]) =
        make_uint2(packh2(wv.x, wv.y), packh2(wv.z, wv.w));
}

// ---------------------------------------------------------------------------
// Kernel 3: flash attention, fp16 mma.sync, m32 rows per warp (4 warps)
// SMEM: Q 16KB | 3 x 8KB K buffers = 40960 B
// ---------------------------------------------------------------------------
constexpr int SM_KB   = 16384;
constexpr int KBUF    = 8192;
constexpr int FL_SMEM = SM_KB + 3 * KBUF;

__global__ void __launch_bounds__(128, 2) flash_mma_kernel() {
    extern __shared__ char smem[];
    const uint32_t sb = smem_u32(smem);
    const int tid = threadIdx.x, lane = tid & 31, w = tid >> 5;
    const int qt = blockIdx.x, h = blockIdx.y, b = blockIdx.z;
    const __half* Af = g_Af + (size_t)(b * Hc + h) * Sc * DKc;

    cpa_tile<128>(sb, Af + qt * 128 * 64, 128, 64, tid);
    CP_COMMIT;
    cpa_tile<128>(sb + SM_KB, Af, 64, 64, tid);
    CP_COMMIT;
    cpa_tile<128>(sb + SM_KB + KBUF, Af + 64 * 64, 64, 64, tid);
    CP_COMMIT;
    CP_WAIT2;                    // Q landed
    __syncthreads();

    // Q fragments for row blocks A (32w..+15) and B (32w+16..+31)
    uint32_t qA[16], qB[16];
    {
        int rowA = 32 * w + (lane & 7) + (((lane >> 3) & 1) << 3);
        int rowB = rowA + 16;
#pragma unroll
        for (int ks = 0; ks < 4; ks++) {
            int c = 2 * ks + (lane >> 4);
            ldsm_x4(qA + ks * 4, sb + rowA * 128 + ((c ^ (rowA & 7)) << 4));
            ldsm_x4(qB + ks * 4, sb + rowB * 128 + ((c ^ (rowB & 7)) << 4));
        }
    }

    float OA[32], OB[32];
#pragma unroll
    for (int i = 0; i < 32; i++) { OA[i] = 0.f; OB[i] = 0.f; }
    float lA0 = 0.f, lA1 = 0.f, lB0 = 0.f, lB1 = 0.f;

    const int brow0 = (lane & 7) + ((lane >> 4) << 3);
    const uint32_t SCL2 = packh2(SCL, SCL);

#pragma unroll 1
    for (int kt = 0; kt < 32; kt++) {
        if (kt == 31) { CP_WAIT0; } else { CP_WAIT1; }
        __syncthreads();
        if (kt + 2 < 32) {
            cpa_tile<128>(sb + SM_KB + ((kt + 2) % 3) * KBUF, Af + (kt + 2) * 64 * 64, 64, 64, tid);
            CP_COMMIT;
        }
        const uint32_t kb = sb + SM_KB + (kt % 3) * KBUF;

        // ---- MMA1: S = Q K^T for both row blocks (K frags loaded once)
        float SA[32], SB[32];
#pragma unroll
        for (int i = 0; i < 32; i++) { SA[i] = 0.f; SB[i] = 0.f; }
#pragma unroll
        for (int ks = 0; ks < 4; ks++) {
            int c = 2 * ks + ((lane >> 3) & 1);
#pragma unroll
            for (int np = 0; np < 4; np++) {
                int r = np * 16 + brow0;
                uint32_t bf[4];
                ldsm_x4(bf, kb + r * 128 + ((c ^ (r & 7)) << 4));
                mma_f16(SA + np * 8,     qA + ks * 4, bf);
                mma_f16(SA + np * 8 + 4, qA + ks * 4, bf + 2);
                mma_f16(SB + np * 8,     qB + ks * 4, bf);
                mma_f16(SB + np * 8 + 4, qB + ks * 4, bf + 2);
            }
        }

        // ---- softmax in f16x2 (bounded; exp output IS the MMA2 A-fragment)
        uint32_t cA[8], dA[8], cB[8], dB[8];
#pragma unroll
        for (int j = 0; j < 8; j++) {
            cA[j] = ex2h2(hmul2(packh2(SA[j * 4 + 0], SA[j * 4 + 1]), SCL2));
            dA[j] = ex2h2(hmul2(packh2(SA[j * 4 + 2], SA[j * 4 + 3]), SCL2));
            cB[j] = ex2h2(hmul2(packh2(SB[j * 4 + 0], SB[j * 4 + 1]), SCL2));
            dB[j] = ex2h2(hmul2(packh2(SB[j * 4 + 2], SB[j * 4 + 3]), SCL2));
        }
        lA0 += h2sumf(hadd2(hadd2(hadd2(cA[0], cA[1]), hadd2(cA[2], cA[3])),
                            hadd2(hadd2(cA[4], cA[5]), hadd2(cA[6], cA[7]))));
        lA1 += h2sumf(hadd2(hadd2(hadd2(dA[0], dA[1]), hadd2(dA[2], dA[3])),
                            hadd2(hadd2(dA[4], dA[5]), hadd2(dA[6], dA[7]))));
        lB0 += h2sumf(hadd2(hadd2(hadd2(cB[0], cB[1]), hadd2(cB[2], cB[3])),
                            hadd2(hadd2(cB[4], cB[5]), hadd2(cB[6], cB[7]))));
        lB1 += h2sumf(hadd2(hadd2(hadd2(dB[0], dB[1]), hadd2(dB[2], dB[3])),
                            hadd2(hadd2(dB[4], dB[5]), hadd2(dB[6], dB[7]))));

        // ---- MMA2: O += P V (V tile == K tile; V frags loaded once)
#pragma unroll
        for (int ks = 0; ks < 4; ks++) {
            uint32_t pfA[4] = { cA[2 * ks], dA[2 * ks], cA[2 * ks + 1], dA[2 * ks + 1] };
            uint32_t pfB[4] = { cB[2 * ks], dB[2 * ks], cB[2 * ks + 1], dB[2 * ks + 1] };
            int vrow = 16 * ks + (lane & 7) + (((lane >> 3) & 1) << 3);
#pragma unroll
            for (int np = 0; np < 4; np++) {
                int c = np * 2 + (lane >> 4);
                uint32_t vf[4];
                ldsm_x4_t(vf, kb + vrow * 128 + ((c ^ (vrow & 7)) << 4));
                mma_f16(OA + np * 8,     pfA, vf);
                mma_f16(OA + np * 8 + 4, pfA, vf + 2);
                mma_f16(OB + np * 8,     pfB, vf);
                mma_f16(OB + np * 8 + 4, pfB, vf + 2);
            }
        }
    }

    // deferred cross-lane l reductions (cols split across lane groups of 4)
#pragma unroll
    for (int off = 1; off <= 2; off <<= 1) {
        lA0 += __shfl_xor_sync(0xffffffffu, lA0, off);
        lA1 += __shfl_xor_sync(0xffffffffu, lA1, off);
        lB0 += __shfl_xor_sync(0xffffffffu, lB0, off);
        lB1 += __shfl_xor_sync(0xffffffffu, lB1, off);
    }

    // ---- normalize + write AO fp16 ([b][s][e], e = h*64+d)
    float iA0 = 1.f / lA0, iA1 = 1.f / lA1, iB0 = 1.f / lB0, iB1 = 1.f / lB1;
    int r0 = qt * 128 + 32 * w + (lane >> 2);
    int colb = h * 64 + 2 * (lane & 3);
#pragma unroll
    for (int j = 0; j < 8; j++) {
        int col = colb + j * 8;
        size_t i0 = (size_t)(b * Sc + r0) * Ec + col;
        *reinterpret_cast<uint32_t*>(&g_AOf[i0]) =
            packh2(OA[j * 4 + 0] * iA0, OA[j * 4 + 1] * iA0);
        *reinterpret_cast<uint32_t*>(&g_AOf[i0 + 8 * Ec]) =
            packh2(OA[j * 4 + 2] * iA1, OA[j * 4 + 3] * iA1);
        *reinterpret_cast<uint32_t*>(&g_AOf[i0 + 16 * Ec]) =
            packh2(OB[j * 4 + 0] * iB0, OB[j * 4 + 1] * iB0);
        *reinterpret_cast<uint32_t*>(&g_AOf[i0 + 24 * Ec]) =
            packh2(OB[j * 4 + 2] * iB1, OB[j * 4 + 3] * iB1);
    }
}

// ---------------------------------------------------------------------------
// Kernel 4: epilogue GEMM out = AO @ W^T + b, single fp16 term
// per chunk buffer: AOf 16K | Wf 8K = 24K; double buffered = 48K
// ---------------------------------------------------------------------------
constexpr int GB = 24576;
constexpr int GEMM_SMEM = 2 * GB;

__global__ void __launch_bounds__(256, 3) gemm_mma_kernel(const float* __restrict__ bias,
                                                          float* __restrict__ out) {
    extern __shared__ char smem[];
    const uint32_t sb = smem_u32(smem);
    const int tid = threadIdx.x, lane = tid & 31, w = tid >> 5;
    const int n0 = blockIdx.x * 64, m0 = blockIdx.y * 128;

    for (int c = 0; c < 2; c++) {
        uint32_t base = sb + c * GB;
        cpa_tile<256>(base,         g_AOf + (size_t)m0 * Ec + c * 64, 128, Ec, tid);
        cpa_tile<256>(base + 16384, g_Wf  + (size_t)n0 * Ec + c * 64,  64, Ec, tid);
        CP_COMMIT;
    }

    float O[32];
#pragma unroll
    for (int i = 0; i < 32; i++) O[i] = 0.f;

#pragma unroll 1
    for (int ch = 0; ch < 8; ch++) {
        if (ch == 7) { CP_WAIT0; } else { CP_WAIT1; }
        __syncthreads();
        uint32_t base = sb + (ch & 1) * GB;

        uint32_t af[16];
        int arow = 16 * w + (lane & 7) + (((lane >> 3) & 1) << 3);
#pragma unroll
        for (int ks = 0; ks < 4; ks++) {
            int c = 2 * ks + (lane >> 4);
            ldsm_x4(af + ks * 4, base + arow * 128 + ((c ^ (arow & 7)) << 4));
        }
        int brow0 = (lane & 7) + ((lane >> 4) << 3);
#pragma unroll
        for (int ks = 0; ks < 4; ks++) {
            int c = 2 * ks + ((lane >> 3) & 1);
#pragma unroll
            for (int np = 0; np < 4; np++) {
                int r = np * 16 + brow0;
                uint32_t bf[4];
                ldsm_x4(bf, base + 16384 + r * 128 + ((c ^ (r & 7)) << 4));
                mma_f16(O + np * 8,     af + ks * 4, bf);
                mma_f16(O + np * 8 + 4, af + ks * 4, bf + 2);
            }
        }
        __syncthreads();
        if (ch + 2 < 8) {
            uint32_t nb2 = sb + (ch & 1) * GB;
            int c2 = ch + 2;
            cpa_tile<256>(nb2,         g_AOf + (size_t)m0 * Ec + c2 * 64, 128, Ec, tid);
            cpa_tile<256>(nb2 + 16384, g_Wf  + (size_t)n0 * Ec + c2 * 64,  64, Ec, tid);
            CP_COMMIT;
        }
    }

    int m = m0 + 16 * w + (lane >> 2);
    int nb = n0 + 2 * (lane & 3);
#pragma unroll
    for (int j = 0; j < 8; j++) {
        int n = nb + j * 8;
        float b0 = bias[n], b1 = bias[n + 1];
        *reinterpret_cast<float2*>(&out[(size_t)m * Ec + n]) =
            make_float2(O[j * 4 + 0] + b0, O[j * 4 + 1] + b1);
        *reinterpret_cast<float2*>(&out[(size_t)(m + 8) * Ec + n]) =
            make_float2(O[j * 4 + 2] + b0, O[j * 4 + 3] + b1);
    }
}

// ---------------------------------------------------------------------------
extern "C" void kernel_launch(void* const* d_in, const int* in_sizes, int n_in,
                              void* d_out, int out_size) {
    const float* x     = (const float*)d_in[0];
    const float* theta = (const float*)d_in[1];
    const float* W     = (const float*)d_in[2];
    const float* bias  = (const float*)d_in[3];
    float* out = (float*)d_out;

    cudaFuncSetAttribute(flash_mma_kernel, cudaFuncAttributeMaxDynamicSharedMemorySize, FL_SMEM);
    cudaFuncSetAttribute(gemm_mma_kernel, cudaFuncAttributeMaxDynamicSharedMemorySize, GEMM_SMEM);

    cos_kernel<<<(Bc * Sc * Ec / 4) / 256, 256>>>(x, theta);
    w_half_kernel<<<(Ec * Ec / 4) / 256, 256>>>(W);

    dim3 fgrid(Sc / 128, Hc, Bc);
    flash_mma_kernel<<<fgrid, 128, FL_SMEM>>>();

    dim3 ggrid(Ec / 64, (Bc * Sc) / 128);
    gemm_mma_kernel<<<ggrid, 256, GEMM_SMEM>>>(bias, out);
}